// round 11
// baseline (speedup 1.0000x reference)
#include <cuda_runtime.h>
#include <math.h>

// ---------------------------------------------------------------
// BSTGCNet R11 = R10 (best: 217.8us) with ONE change:
// gx pass loop no longer cross-unrolled (#pragma unroll 1) and
// __launch_bounds__(192,5) caps regs -> occupancy 18% -> ~45%.
// B=8, T=12, N=512, FIN=2, H=64, P=12
// ---------------------------------------------------------------

typedef unsigned long long ull;

__device__ __forceinline__ ull fma2(ull a, ull b, ull c) {
    ull d; asm("fma.rn.f32x2 %0, %1, %2, %3;" : "=l"(d) : "l"(a), "l"(b), "l"(c)); return d;
}
__device__ __forceinline__ float hsum2(ull v) {
    float a, b; asm("mov.b64 {%0, %1}, %2;" : "=f"(a), "=f"(b) : "l"(v)); return a + b;
}

__device__ unsigned g_mask[3 * 512 * 16];       // packed adjacency bits
__device__ float g_feat[96 * 512 * 128];        // [f_s | f_nd] concat
__device__ float g_spatial[96 * 512 * 64];      // relu(concat@Wf+bf)
__device__ float g_gx[4096 * 12 * 192];         // input transform for GRU
__device__ ulonglong2 g_WfT2[32 * 64];          // Wf  [k4][h]
__device__ ulonglong2 g_WihT2[17 * 192];        // Wih [k4][g], k>=66 -> 0

#define SMEM_K1 ((512*2 + 512*4*2 + 3*128*2) * 4)            // 25600
#define SMEM_B1 (64*32*16)                                   // 32768
#define SMEM_B2 (32*17*16)                                   // 8704
#define SMEM_C  (32*192*8 + 2*32*64*4 + 32*32*4)             // 69632

// ----------------- prep: bitmasks + weight transposes -----------------
// grid (4, 64), block 256. g<3: maskpack rows; g==3: wprep.
__global__ void prep_kernel(const int* __restrict__ Gs, const int* __restrict__ Gn,
                            const int* __restrict__ Gd,
                            const float* __restrict__ Wf, const float* __restrict__ Wih)
{
    const int g = blockIdx.x;
    if (g < 3) {
        const int row = blockIdx.y * 8 + (threadIdx.x >> 5);
        const int lane = threadIdx.x & 31;
        const int* adj = (g == 0) ? Gs : (g == 1) ? Gn : Gd;
        const int* arow = adj + row * 512;
#pragma unroll
        for (int it = 0; it < 16; ++it) {
            unsigned m = __ballot_sync(0xffffffffu, arow[it * 32 + lane] > 0);
            if (lane == 0) g_mask[(g * 512 + row) * 16 + it] = m;
        }
    } else {
        const int tid = blockIdx.y * 256 + threadIdx.x;
        if (tid < 32 * 64) {
            int k4 = tid >> 6, h = tid & 63;
            float4 v = make_float4(Wf[(4 * k4 + 0) * 64 + h], Wf[(4 * k4 + 1) * 64 + h],
                                   Wf[(4 * k4 + 2) * 64 + h], Wf[(4 * k4 + 3) * 64 + h]);
            g_WfT2[tid] = *(ulonglong2*)&v;
        }
        int t2 = tid - 32 * 64;
        if (t2 >= 0 && t2 < 17 * 192) {
            int k4 = t2 / 192, gg = t2 - k4 * 192;
            float w[4];
#pragma unroll
            for (int j = 0; j < 4; ++j) {
                int k = 4 * k4 + j;
                w[j] = (k < 66) ? Wih[gg * 66 + k] : 0.f;
            }
            g_WihT2[t2] = *(ulonglong2*)w;
        }
    }
}

// ----------------- K1: 3x GAT (rank-2) + concat features -----------------
// grid (96, 4), block 256. Each block: one m, 128 rows, all 3 gats.
__global__ void gat_kernel(const float* __restrict__ X,
                           const float* __restrict__ Wg, const float* __restrict__ a1g, const float* __restrict__ a2g,
                           const float* __restrict__ Wn, const float* __restrict__ a1n, const float* __restrict__ a2n,
                           const float* __restrict__ Wd, const float* __restrict__ a1d, const float* __restrict__ a2d)
{
    extern __shared__ float sm[];
    float*  x0s = sm;                       // 512
    float*  x1s = sm + 512;                 // 512
    float4* P4  = (float4*)(sm + 1024);     // 512  {E1*x0, E1*x1, E1, s2}
    float4* Q4  = P4 + 512;                 // 512  {E2*x0, E2*x1, E2, 0}
    float2* yg  = (float2*)(Q4 + 512);      // [3][128]

    const int m = blockIdx.x;
    const int row0 = blockIdx.y * 128;
    const int tid = threadIdx.x;
    const int lane = tid & 31, wid = tid >> 5;

    const float* Ws[3]  = {Wg, Wn, Wd};
    const float* A1s[3] = {a1g, a1n, a1d};
    const float* A2s[3] = {a2g, a2n, a2d};

    for (int i = tid; i < 512; i += 256) {
        x0s[i] = X[(m * 512 + i) * 2];
        x1s[i] = X[(m * 512 + i) * 2 + 1];
    }

    for (int g = 0; g < 3; ++g) {
        const float* W  = Ws[g];
        const float* a1 = A1s[g];
        const float* a2 = A2s[g];
        float c1a = 0.f, c1b = 0.f, c2a = 0.f, c2b = 0.f;
#pragma unroll 8
        for (int k = 0; k < 64; ++k) {
            float A1 = __ldg(a1 + k), A2 = __ldg(a2 + k);
            float u = __ldg(W + k), v = __ldg(W + 64 + k);
            c1a += u * A1; c1b += v * A1; c2a += u * A2; c2b += v * A2;
        }
        __syncthreads();
        for (int j = tid; j < 512; j += 256) {
            float x0 = x0s[j], x1 = x1s[j];
            float s2 = x0 * c2a + x1 * c2b;
            float E1 = __expf(s2);
            float E2 = __expf(0.2f * s2);
            P4[j] = make_float4(E1 * x0, E1 * x1, E1, s2);
            Q4[j] = make_float4(E2 * x0, E2 * x1, E2, 0.f);
        }
        __syncthreads();

        // 16 rows per warp, 4 rows per sweep
        for (int g4 = 0; g4 < 4; ++g4) {
            int rlb = wid * 16 + g4 * 4;
            float thr[4], Ae[4], Be[4];
            const unsigned* mr[4];
#pragma unroll
            for (int r = 0; r < 4; ++r) {
                int i = row0 + rlb + r;
                float s1 = x0s[i] * c1a + x1s[i] * c1b;
                thr[r] = -s1;
                Ae[r] = __expf(s1);
                Be[r] = __expf(0.2f * s1);
                mr[r] = g_mask + (g * 512 + i) * 16;
            }
            float a0[4], a1v[4], a2v[4], b0[4], b1v[4], b2v[4];
#pragma unroll
            for (int r = 0; r < 4; ++r) {
                a0[r] = a1v[r] = a2v[r] = 0.f;
                b0[r] = b1v[r] = b2v[r] = 0.f;
            }
            for (int it = 0; it < 16; ++it) {
                int j = it * 32 + lane;
                float4 p = P4[j];
                float4 q = Q4[j];
#pragma unroll
                for (int r = 0; r < 4; ++r) {
                    unsigned mw = __ldg(mr[r] + it);
                    if ((mw >> lane) & 1u) {
                        if (p.w > thr[r]) { a0[r] += p.x; a1v[r] += p.y; a2v[r] += p.z; }
                        else              { b0[r] += q.x; b1v[r] += q.y; b2v[r] += q.z; }
                    }
                }
            }
#pragma unroll
            for (int r = 0; r < 4; ++r) {
                float y0 = Ae[r] * a0[r] + Be[r] * b0[r];
                float y1 = Ae[r] * a1v[r] + Be[r] * b1v[r];
                float Z  = Ae[r] * a2v[r] + Be[r] * b2v[r];
#pragma unroll
                for (int o = 16; o; o >>= 1) {
                    y0 += __shfl_xor_sync(0xffffffffu, y0, o);
                    y1 += __shfl_xor_sync(0xffffffffu, y1, o);
                    Z  += __shfl_xor_sync(0xffffffffu, Z, o);
                }
                if (lane == 0) {
                    float zi = __fdividef(1.f, Z);
                    yg[g * 128 + rlb + r] = make_float2(y0 * zi, y1 * zi);
                }
            }
        }
    }
    __syncthreads();

    const int h = tid & 63;
    const float wg0 = __ldg(Wg + h), wg1 = __ldg(Wg + 64 + h);
    const float wn0 = __ldg(Wn + h), wn1 = __ldg(Wn + 64 + h);
    const float wd0 = __ldg(Wd + h), wd1 = __ldg(Wd + 64 + h);
#pragma unroll 4
    for (int it = 0; it < 32; ++it) {
        int rl = (tid >> 6) + it * 4;
        float2 ys = yg[rl], yn = yg[128 + rl], yd = yg[256 + rl];
        float vs = ys.x * wg0 + ys.y * wg1;
        vs = (vs > 0.f) ? vs : (__expf(vs) - 1.f);
        float vn = yn.x * wn0 + yn.y * wn1;
        vn = (vn > 0.f) ? vn : (__expf(vn) - 1.f);
        float vd = yd.x * wd0 + yd.y * wd1;
        vd = (vd > 0.f) ? vd : (__expf(vd) - 1.f);
        int gi = (m * 512 + row0 + rl) * 128;
        g_feat[gi + h] = vs;
        g_feat[gi + 64 + h] = vn + vd;
    }
}

// ----------------- B1: spatial fuse -----------------
// grid (96, 8), block 256, 64 rows/block. Each thread: 2 h-cols x 8 rows.
__global__ void spatial_kernel(const float* __restrict__ bf)
{
    extern __shared__ ulonglong2 smu[];      // feat rows [64][32]
    const int m = blockIdx.x, row0 = blockIdx.y * 64;
    const int tid = threadIdx.x, lane = tid & 31, rg = tid >> 5;

    const float4* src = (const float4*)(g_feat + (m * 512 + row0) * 128);
    float4* dst = (float4*)smu;
    for (int idx = tid; idx < 64 * 32; idx += 256) dst[idx] = src[idx];
    __syncthreads();

    const float bha = __ldg(bf + lane), bhb = __ldg(bf + 32 + lane);
    ull acca[8], accb[8];
#pragma unroll
    for (int r = 0; r < 8; ++r) { acca[r] = 0ull; accb[r] = 0ull; }
#pragma unroll 4
    for (int k4 = 0; k4 < 32; ++k4) {
        ulonglong2 wa = __ldg(&g_WfT2[k4 * 64 + lane]);
        ulonglong2 wb = __ldg(&g_WfT2[k4 * 64 + 32 + lane]);
#pragma unroll
        for (int r = 0; r < 8; ++r) {
            ulonglong2 fv = smu[(rg * 8 + r) * 32 + k4];
            acca[r] = fma2(wa.x, fv.x, acca[r]);
            acca[r] = fma2(wa.y, fv.y, acca[r]);
            accb[r] = fma2(wb.x, fv.x, accb[r]);
            accb[r] = fma2(wb.y, fv.y, accb[r]);
        }
    }
#pragma unroll
    for (int r = 0; r < 8; ++r) {
        float* orow = g_spatial + (m * 512 + row0 + rg * 8 + r) * 64;
        orow[lane]      = fmaxf(hsum2(acca[r]) + bha, 0.f);
        orow[32 + lane] = fmaxf(hsum2(accb[r]) + bhb, 0.f);
    }
}

// ----------------- B2: gx = [spatial,x] @ W_ih^T + b_ih -----------------
// grid (96, 16), block 192, 32 rows/block, 4 passes of 8 rows (NOT
// cross-unrolled; reg-capped for 5 CTAs/SM).
__global__ void __launch_bounds__(192, 5) gx_kernel(const float* __restrict__ X,
                                                    const float* __restrict__ bih)
{
    extern __shared__ ulonglong2 smu[];      // gru_in rows [32][17]
    float* smf = (float*)smu;
    const int m = blockIdx.x;
    const int b = m / 12, t = m - b * 12;
    const int row0 = blockIdx.y * 32;
    const int tid = threadIdx.x;             // = gate dim g

    for (int idx = tid; idx < 32 * 68; idx += 192) {
        int r = idx / 68, k = idx - r * 68;
        float v;
        if (k < 64)      v = g_spatial[(m * 512 + row0 + r) * 64 + k];
        else if (k < 66) v = X[(m * 512 + row0 + r) * 2 + (k - 64)];
        else             v = 0.f;
        smf[idx] = v;
    }
    __syncthreads();

    const int g = tid;
    const float bg = __ldg(bih + g);
    float* gxout = g_gx + ((b * 512 + row0) * 12 + t) * 192 + g;

#pragma unroll 1
    for (int pass = 0; pass < 4; ++pass) {
        ull acc2[8];
#pragma unroll
        for (int r = 0; r < 8; ++r) acc2[r] = 0ull;
#pragma unroll
        for (int k4 = 0; k4 < 17; ++k4) {
            ulonglong2 wv = __ldg(&g_WihT2[k4 * 192 + g]);
#pragma unroll
            for (int r = 0; r < 8; ++r) {
                ulonglong2 hv = smu[(pass * 8 + r) * 17 + k4];
                acc2[r] = fma2(wv.x, hv.x, acc2[r]);
                acc2[r] = fma2(wv.y, hv.y, acc2[r]);
            }
        }
#pragma unroll
        for (int r = 0; r < 8; ++r)
            gxout[(pass * 8 + r) * 12 * 192] = hsum2(acc2[r]) + bg;
    }
}

// ----------------- K3: GRU recurrence + heads -----------------
// grid 128, block 256. 32 seqs/block, 8 seqs per thread group.
__global__ void gru_kernel(const float* __restrict__ Whh, const float* __restrict__ bhh,
                           const float* __restrict__ W1, const float* __restrict__ b1,
                           const float* __restrict__ W2, const float* __restrict__ b2,
                           float* __restrict__ out)
{
    extern __shared__ float sm[];
    float* wt  = sm;                    // [32][192][2]
    float* hs0 = sm + 12288;            // [32][64]
    float* hs1 = hs0 + 32 * 64;         // [32][64]
    float* t1  = hs1 + 32 * 64;         // [32][32]
    const int tid = threadIdx.x;
    const int h = tid & 63, sg = tid >> 6;

    for (int idx = tid; idx < 12288; idx += 256) {
        int e = idx & 1, rest = idx >> 1;
        int row = rest % 192, k2 = rest / 192;
        wt[idx] = Whh[row * 64 + k2 * 2 + e];
    }
    for (int idx = tid; idx < 32 * 64; idx += 256) hs0[idx] = 0.f;
    __syncthreads();

    const float bhr = bhh[h], bhz = bhh[64 + h], bhn = bhh[128 + h];
    const int s0 = blockIdx.x * 32;
    const ull* wp = (const ull*)wt;

    for (int t = 0; t < 12; ++t) {
        float* cur = (t & 1) ? hs1 : hs0;
        float* nxt = (t & 1) ? hs0 : hs1;

        float gxr[8], gxz[8], gxn[8];
#pragma unroll
        for (int si = 0; si < 8; ++si) {
            const float* gxp = g_gx + ((s0 + sg * 8 + si) * 12 + t) * 192;
            gxr[si] = gxp[h]; gxz[si] = gxp[64 + h]; gxn[si] = gxp[128 + h];
        }

        ull ar2[8], az2[8], an2[8];
#pragma unroll
        for (int si = 0; si < 8; ++si) { ar2[si] = 0ull; az2[si] = 0ull; an2[si] = 0ull; }
        const ull* hc = (const ull*)(cur + sg * 8 * 64);
#pragma unroll 4
        for (int k2 = 0; k2 < 32; ++k2) {
            ull wr = wp[k2 * 192 + h];
            ull wz = wp[k2 * 192 + 64 + h];
            ull wn = wp[k2 * 192 + 128 + h];
#pragma unroll
            for (int si = 0; si < 8; ++si) {
                ull hp = hc[si * 32 + k2];
                ar2[si] = fma2(wr, hp, ar2[si]);
                az2[si] = fma2(wz, hp, az2[si]);
                an2[si] = fma2(wn, hp, an2[si]);
            }
        }
#pragma unroll
        for (int si = 0; si < 8; ++si) {
            int sl = sg * 8 + si;
            float r = __fdividef(1.f, 1.f + __expf(-(gxr[si] + hsum2(ar2[si]) + bhr)));
            float z = __fdividef(1.f, 1.f + __expf(-(gxz[si] + hsum2(az2[si]) + bhz)));
            float narg = gxn[si] + r * (hsum2(an2[si]) + bhn);
            float ex = __expf(-2.f * narg);
            float n = 1.f - __fdividef(2.f * ex, 1.f + ex);
            float hp = cur[sl * 64 + h];
            nxt[sl * 64 + h] = (1.f - z) * n + z * hp;
        }
        __syncthreads();
    }

    // heads: relu(h@W1+b1)@W2+b2 ; final h in hs0 (T=12 even)
    for (int idx = tid; idx < 32 * 32; idx += 256) {
        int sl = idx >> 5, j = idx & 31;
        float a = b1[j];
        const float* hrow = hs0 + sl * 64;
#pragma unroll 8
        for (int k = 0; k < 64; ++k) a += hrow[k] * W1[k * 32 + j];
        t1[sl * 32 + j] = fmaxf(a, 0.f);
    }
    __syncthreads();
    for (int idx = tid; idx < 32 * 12; idx += 256) {
        int sl = idx / 12, p = idx - sl * 12;
        float a = b2[p];
        const float* trow = t1 + sl * 32;
#pragma unroll 8
        for (int k = 0; k < 32; ++k) a += trow[k] * W2[k * 12 + p];
        int sgl = s0 + sl;
        int bb = sgl >> 9, n = sgl & 511;
        out[(bb * 12 + p) * 512 + n] = a;
    }
}

extern "C" void kernel_launch(void* const* d_in, const int* in_sizes, int n_in,
                              void* d_out, int out_size)
{
    const float* X   = (const float*)d_in[0];
    const int*   Gs  = (const int*)d_in[1];
    const int*   Gn  = (const int*)d_in[2];
    const int*   Gd  = (const int*)d_in[3];
    const float* Wg  = (const float*)d_in[4];
    const float* a1g = (const float*)d_in[5];
    const float* a2g = (const float*)d_in[6];
    const float* Wn  = (const float*)d_in[7];
    const float* a1n = (const float*)d_in[8];
    const float* a2n = (const float*)d_in[9];
    const float* Wd  = (const float*)d_in[10];
    const float* a1d = (const float*)d_in[11];
    const float* a2d = (const float*)d_in[12];
    const float* Wf  = (const float*)d_in[13];
    const float* bf  = (const float*)d_in[14];
    const float* Wih = (const float*)d_in[15];
    const float* Whh = (const float*)d_in[16];
    const float* bih = (const float*)d_in[17];
    const float* bhh = (const float*)d_in[18];
    const float* W1  = (const float*)d_in[19];
    const float* b1  = (const float*)d_in[20];
    const float* W2  = (const float*)d_in[21];
    const float* b2  = (const float*)d_in[22];
    float* out = (float*)d_out;

    cudaFuncSetAttribute(gat_kernel,     cudaFuncAttributeMaxDynamicSharedMemorySize, SMEM_K1);
    cudaFuncSetAttribute(spatial_kernel, cudaFuncAttributeMaxDynamicSharedMemorySize, SMEM_B1);
    cudaFuncSetAttribute(gx_kernel,      cudaFuncAttributeMaxDynamicSharedMemorySize, SMEM_B2);
    cudaFuncSetAttribute(gru_kernel,     cudaFuncAttributeMaxDynamicSharedMemorySize, SMEM_C);

    prep_kernel<<<dim3(4, 64), 256>>>(Gs, Gn, Gd, Wf, Wih);
    gat_kernel<<<dim3(96, 4), 256, SMEM_K1>>>(X, Wg, a1g, a2g, Wn, a1n, a2n, Wd, a1d, a2d);
    spatial_kernel<<<dim3(96, 8), 256, SMEM_B1>>>(bf);
    gx_kernel<<<dim3(96, 16), 192, SMEM_B2>>>(X, bih);
    gru_kernel<<<128, 256, SMEM_C>>>(Whh, bhh, W1, b1, W2, b2, out);
}

// round 12
// speedup vs baseline: 1.2280x; 1.2280x over previous
#include <cuda_runtime.h>
#include <math.h>

// ---------------------------------------------------------------
// BSTGCNet R12 = R10 (best: 217.8us) with gat-only change:
// grid (96,8) / 64 rows per block (2x resident warps) and uint4
// mask loads (mask LDG count / 4). gx stays the R10 local optimum.
// B=8, T=12, N=512, FIN=2, H=64, P=12
// ---------------------------------------------------------------

typedef unsigned long long ull;

__device__ __forceinline__ ull fma2(ull a, ull b, ull c) {
    ull d; asm("fma.rn.f32x2 %0, %1, %2, %3;" : "=l"(d) : "l"(a), "l"(b), "l"(c)); return d;
}
__device__ __forceinline__ float hsum2(ull v) {
    float a, b; asm("mov.b64 {%0, %1}, %2;" : "=f"(a), "=f"(b) : "l"(v)); return a + b;
}

__device__ unsigned g_mask[3 * 512 * 16];       // packed adjacency bits
__device__ float g_feat[96 * 512 * 128];        // [f_s | f_nd] concat
__device__ float g_spatial[96 * 512 * 64];      // relu(concat@Wf+bf)
__device__ float g_gx[4096 * 12 * 192];         // input transform for GRU
__device__ ulonglong2 g_WfT2[32 * 64];          // Wf  [k4][h]
__device__ ulonglong2 g_WihT2[17 * 192];        // Wih [k4][g], k>=66 -> 0

#define SMEM_K1 ((512*2 + 512*4*2 + 3*64*2) * 4)             // 22016
#define SMEM_B1 (64*32*16)                                   // 32768
#define SMEM_B2 (32*17*16)                                   // 8704
#define SMEM_C  (32*192*8 + 2*32*64*4 + 32*32*4)             // 69632

// ----------------- prep: bitmasks + weight transposes -----------------
__global__ void prep_kernel(const int* __restrict__ Gs, const int* __restrict__ Gn,
                            const int* __restrict__ Gd,
                            const float* __restrict__ Wf, const float* __restrict__ Wih)
{
    const int g = blockIdx.x;
    if (g < 3) {
        const int row = blockIdx.y * 8 + (threadIdx.x >> 5);
        const int lane = threadIdx.x & 31;
        const int* adj = (g == 0) ? Gs : (g == 1) ? Gn : Gd;
        const int* arow = adj + row * 512;
#pragma unroll
        for (int it = 0; it < 16; ++it) {
            unsigned m = __ballot_sync(0xffffffffu, arow[it * 32 + lane] > 0);
            if (lane == 0) g_mask[(g * 512 + row) * 16 + it] = m;
        }
    } else {
        const int tid = blockIdx.y * 256 + threadIdx.x;
        if (tid < 32 * 64) {
            int k4 = tid >> 6, h = tid & 63;
            float4 v = make_float4(Wf[(4 * k4 + 0) * 64 + h], Wf[(4 * k4 + 1) * 64 + h],
                                   Wf[(4 * k4 + 2) * 64 + h], Wf[(4 * k4 + 3) * 64 + h]);
            g_WfT2[tid] = *(ulonglong2*)&v;
        }
        int t2 = tid - 32 * 64;
        if (t2 >= 0 && t2 < 17 * 192) {
            int k4 = t2 / 192, gg = t2 - k4 * 192;
            float w[4];
#pragma unroll
            for (int j = 0; j < 4; ++j) {
                int k = 4 * k4 + j;
                w[j] = (k < 66) ? Wih[gg * 66 + k] : 0.f;
            }
            g_WihT2[t2] = *(ulonglong2*)w;
        }
    }
}

// ----------------- K1: 3x GAT (rank-2) + concat features -----------------
// grid (96, 8), block 256. Each block: one m, 64 rows, all 3 gats.
// 8 rows per warp: two 4-row sweeps; masks loaded as uint4.
__global__ void gat_kernel(const float* __restrict__ X,
                           const float* __restrict__ Wg, const float* __restrict__ a1g, const float* __restrict__ a2g,
                           const float* __restrict__ Wn, const float* __restrict__ a1n, const float* __restrict__ a2n,
                           const float* __restrict__ Wd, const float* __restrict__ a1d, const float* __restrict__ a2d)
{
    extern __shared__ float sm[];
    float*  x0s = sm;                       // 512
    float*  x1s = sm + 512;                 // 512
    float4* P4  = (float4*)(sm + 1024);     // 512  {E1*x0, E1*x1, E1, s2}
    float4* Q4  = P4 + 512;                 // 512  {E2*x0, E2*x1, E2, 0}
    float2* yg  = (float2*)(Q4 + 512);      // [3][64]

    const int m = blockIdx.x;
    const int row0 = blockIdx.y * 64;
    const int tid = threadIdx.x;
    const int lane = tid & 31, wid = tid >> 5;

    const float* Ws[3]  = {Wg, Wn, Wd};
    const float* A1s[3] = {a1g, a1n, a1d};
    const float* A2s[3] = {a2g, a2n, a2d};

    for (int i = tid; i < 512; i += 256) {
        x0s[i] = __ldg(X + (m * 512 + i) * 2);
        x1s[i] = __ldg(X + (m * 512 + i) * 2 + 1);
    }

    for (int g = 0; g < 3; ++g) {
        const float* W  = Ws[g];
        const float* a1 = A1s[g];
        const float* a2 = A2s[g];
        float c1a = 0.f, c1b = 0.f, c2a = 0.f, c2b = 0.f;
#pragma unroll 8
        for (int k = 0; k < 64; ++k) {
            float A1 = __ldg(a1 + k), A2 = __ldg(a2 + k);
            float u = __ldg(W + k), v = __ldg(W + 64 + k);
            c1a += u * A1; c1b += v * A1; c2a += u * A2; c2b += v * A2;
        }
        __syncthreads();
        for (int j = tid; j < 512; j += 256) {
            float x0 = x0s[j], x1 = x1s[j];
            float s2 = x0 * c2a + x1 * c2b;
            float E1 = __expf(s2);
            float E2 = __expf(0.2f * s2);
            P4[j] = make_float4(E1 * x0, E1 * x1, E1, s2);
            Q4[j] = make_float4(E2 * x0, E2 * x1, E2, 0.f);
        }
        __syncthreads();

        // 8 rows per warp, two 4-row sweeps
        for (int g4 = 0; g4 < 2; ++g4) {
            int rlb = wid * 8 + g4 * 4;
            float thr[4], Ae[4], Be[4];
            const uint4* mr4[4];
#pragma unroll
            for (int r = 0; r < 4; ++r) {
                int i = row0 + rlb + r;
                float s1 = x0s[i] * c1a + x1s[i] * c1b;
                thr[r] = -s1;
                Ae[r] = __expf(s1);
                Be[r] = __expf(0.2f * s1);
                mr4[r] = (const uint4*)(g_mask + (g * 512 + i) * 16);
            }
            float a0[4], a1v[4], a2v[4], b0[4], b1v[4], b2v[4];
#pragma unroll
            for (int r = 0; r < 4; ++r) {
                a0[r] = a1v[r] = a2v[r] = 0.f;
                b0[r] = b1v[r] = b2v[r] = 0.f;
            }
#pragma unroll
            for (int it4 = 0; it4 < 4; ++it4) {
                uint4 mw4[4];
#pragma unroll
                for (int r = 0; r < 4; ++r) mw4[r] = __ldg(mr4[r] + it4);
#pragma unroll
                for (int sub = 0; sub < 4; ++sub) {
                    int j = it4 * 128 + sub * 32 + lane;
                    float4 p = P4[j];
                    float4 q = Q4[j];
#pragma unroll
                    for (int r = 0; r < 4; ++r) {
                        unsigned mw = (&mw4[r].x)[sub];
                        if ((mw >> lane) & 1u) {
                            if (p.w > thr[r]) { a0[r] += p.x; a1v[r] += p.y; a2v[r] += p.z; }
                            else              { b0[r] += q.x; b1v[r] += q.y; b2v[r] += q.z; }
                        }
                    }
                }
            }
#pragma unroll
            for (int r = 0; r < 4; ++r) {
                float y0 = Ae[r] * a0[r] + Be[r] * b0[r];
                float y1 = Ae[r] * a1v[r] + Be[r] * b1v[r];
                float Z  = Ae[r] * a2v[r] + Be[r] * b2v[r];
#pragma unroll
                for (int o = 16; o; o >>= 1) {
                    y0 += __shfl_xor_sync(0xffffffffu, y0, o);
                    y1 += __shfl_xor_sync(0xffffffffu, y1, o);
                    Z  += __shfl_xor_sync(0xffffffffu, Z, o);
                }
                if (lane == 0) {
                    float zi = __fdividef(1.f, Z);
                    yg[g * 64 + rlb + r] = make_float2(y0 * zi, y1 * zi);
                }
            }
        }
        __syncthreads();
    }

    const int h = tid & 63;
    const float wg0 = __ldg(Wg + h), wg1 = __ldg(Wg + 64 + h);
    const float wn0 = __ldg(Wn + h), wn1 = __ldg(Wn + 64 + h);
    const float wd0 = __ldg(Wd + h), wd1 = __ldg(Wd + 64 + h);
#pragma unroll 4
    for (int it = 0; it < 16; ++it) {
        int rl = (tid >> 6) + it * 4;
        float2 ys = yg[rl], yn = yg[64 + rl], yd = yg[128 + rl];
        float vs = ys.x * wg0 + ys.y * wg1;
        vs = (vs > 0.f) ? vs : (__expf(vs) - 1.f);
        float vn = yn.x * wn0 + yn.y * wn1;
        vn = (vn > 0.f) ? vn : (__expf(vn) - 1.f);
        float vd = yd.x * wd0 + yd.y * wd1;
        vd = (vd > 0.f) ? vd : (__expf(vd) - 1.f);
        int gi = (m * 512 + row0 + rl) * 128;
        g_feat[gi + h] = vs;
        g_feat[gi + 64 + h] = vn + vd;
    }
}

// ----------------- B1: spatial fuse -----------------
// grid (96, 8), block 256, 64 rows/block. Each thread: 2 h-cols x 8 rows.
__global__ void spatial_kernel(const float* __restrict__ bf)
{
    extern __shared__ ulonglong2 smu[];      // feat rows [64][32]
    const int m = blockIdx.x, row0 = blockIdx.y * 64;
    const int tid = threadIdx.x, lane = tid & 31, rg = tid >> 5;

    const float4* src = (const float4*)(g_feat + (m * 512 + row0) * 128);
    float4* dst = (float4*)smu;
    for (int idx = tid; idx < 64 * 32; idx += 256) dst[idx] = src[idx];
    __syncthreads();

    const float bha = __ldg(bf + lane), bhb = __ldg(bf + 32 + lane);
    ull acca[8], accb[8];
#pragma unroll
    for (int r = 0; r < 8; ++r) { acca[r] = 0ull; accb[r] = 0ull; }
#pragma unroll 4
    for (int k4 = 0; k4 < 32; ++k4) {
        ulonglong2 wa = __ldg(&g_WfT2[k4 * 64 + lane]);
        ulonglong2 wb = __ldg(&g_WfT2[k4 * 64 + 32 + lane]);
#pragma unroll
        for (int r = 0; r < 8; ++r) {
            ulonglong2 fv = smu[(rg * 8 + r) * 32 + k4];
            acca[r] = fma2(wa.x, fv.x, acca[r]);
            acca[r] = fma2(wa.y, fv.y, acca[r]);
            accb[r] = fma2(wb.x, fv.x, accb[r]);
            accb[r] = fma2(wb.y, fv.y, accb[r]);
        }
    }
#pragma unroll
    for (int r = 0; r < 8; ++r) {
        float* orow = g_spatial + (m * 512 + row0 + rg * 8 + r) * 64;
        orow[lane]      = fmaxf(hsum2(acca[r]) + bha, 0.f);
        orow[32 + lane] = fmaxf(hsum2(accb[r]) + bhb, 0.f);
    }
}

// ----------------- B2: gx = [spatial,x] @ W_ih^T + b_ih -----------------
// grid (96, 16), block 192, 32 rows/block, 4 passes of 8 rows.
// Full cross-pass unroll (weights live in regs; 64 fma2 per weight LDG).
__global__ void gx_kernel(const float* __restrict__ X, const float* __restrict__ bih)
{
    extern __shared__ ulonglong2 smu[];      // gru_in rows [32][17]
    float* smf = (float*)smu;
    const int m = blockIdx.x;
    const int b = m / 12, t = m - b * 12;
    const int row0 = blockIdx.y * 32;
    const int tid = threadIdx.x;             // = gate dim g

    for (int idx = tid; idx < 32 * 68; idx += 192) {
        int r = idx / 68, k = idx - r * 68;
        float v;
        if (k < 64)      v = g_spatial[(m * 512 + row0 + r) * 64 + k];
        else if (k < 66) v = X[(m * 512 + row0 + r) * 2 + (k - 64)];
        else             v = 0.f;
        smf[idx] = v;
    }
    __syncthreads();

    const int g = tid;
    const float bg = __ldg(bih + g);
    float* gxout = g_gx + ((b * 512 + row0) * 12 + t) * 192 + g;

#pragma unroll
    for (int pass = 0; pass < 4; ++pass) {
        ull acc2[8];
#pragma unroll
        for (int r = 0; r < 8; ++r) acc2[r] = 0ull;
#pragma unroll
        for (int k4 = 0; k4 < 17; ++k4) {
            ulonglong2 wv = __ldg(&g_WihT2[k4 * 192 + g]);
#pragma unroll
            for (int r = 0; r < 8; ++r) {
                ulonglong2 hv = smu[(pass * 8 + r) * 17 + k4];
                acc2[r] = fma2(wv.x, hv.x, acc2[r]);
                acc2[r] = fma2(wv.y, hv.y, acc2[r]);
            }
        }
#pragma unroll
        for (int r = 0; r < 8; ++r)
            gxout[(pass * 8 + r) * 12 * 192] = hsum2(acc2[r]) + bg;
    }
}

// ----------------- K3: GRU recurrence + heads -----------------
// grid 128, block 256. 32 seqs/block, 8 seqs per thread group.
__global__ void gru_kernel(const float* __restrict__ Whh, const float* __restrict__ bhh,
                           const float* __restrict__ W1, const float* __restrict__ b1,
                           const float* __restrict__ W2, const float* __restrict__ b2,
                           float* __restrict__ out)
{
    extern __shared__ float sm[];
    float* wt  = sm;                    // [32][192][2]
    float* hs0 = sm + 12288;            // [32][64]
    float* hs1 = hs0 + 32 * 64;         // [32][64]
    float* t1  = hs1 + 32 * 64;         // [32][32]
    const int tid = threadIdx.x;
    const int h = tid & 63, sg = tid >> 6;

    for (int idx = tid; idx < 12288; idx += 256) {
        int e = idx & 1, rest = idx >> 1;
        int row = rest % 192, k2 = rest / 192;
        wt[idx] = Whh[row * 64 + k2 * 2 + e];
    }
    for (int idx = tid; idx < 32 * 64; idx += 256) hs0[idx] = 0.f;
    __syncthreads();

    const float bhr = bhh[h], bhz = bhh[64 + h], bhn = bhh[128 + h];
    const int s0 = blockIdx.x * 32;
    const ull* wp = (const ull*)wt;

    for (int t = 0; t < 12; ++t) {
        float* cur = (t & 1) ? hs1 : hs0;
        float* nxt = (t & 1) ? hs0 : hs1;

        float gxr[8], gxz[8], gxn[8];
#pragma unroll
        for (int si = 0; si < 8; ++si) {
            const float* gxp = g_gx + ((s0 + sg * 8 + si) * 12 + t) * 192;
            gxr[si] = gxp[h]; gxz[si] = gxp[64 + h]; gxn[si] = gxp[128 + h];
        }

        ull ar2[8], az2[8], an2[8];
#pragma unroll
        for (int si = 0; si < 8; ++si) { ar2[si] = 0ull; az2[si] = 0ull; an2[si] = 0ull; }
        const ull* hc = (const ull*)(cur + sg * 8 * 64);
#pragma unroll 4
        for (int k2 = 0; k2 < 32; ++k2) {
            ull wr = wp[k2 * 192 + h];
            ull wz = wp[k2 * 192 + 64 + h];
            ull wn = wp[k2 * 192 + 128 + h];
#pragma unroll
            for (int si = 0; si < 8; ++si) {
                ull hp = hc[si * 32 + k2];
                ar2[si] = fma2(wr, hp, ar2[si]);
                az2[si] = fma2(wz, hp, az2[si]);
                an2[si] = fma2(wn, hp, an2[si]);
            }
        }
#pragma unroll
        for (int si = 0; si < 8; ++si) {
            int sl = sg * 8 + si;
            float r = __fdividef(1.f, 1.f + __expf(-(gxr[si] + hsum2(ar2[si]) + bhr)));
            float z = __fdividef(1.f, 1.f + __expf(-(gxz[si] + hsum2(az2[si]) + bhz)));
            float narg = gxn[si] + r * (hsum2(an2[si]) + bhn);
            float ex = __expf(-2.f * narg);
            float n = 1.f - __fdividef(2.f * ex, 1.f + ex);
            float hp = cur[sl * 64 + h];
            nxt[sl * 64 + h] = (1.f - z) * n + z * hp;
        }
        __syncthreads();
    }

    // heads: relu(h@W1+b1)@W2+b2 ; final h in hs0 (T=12 even)
    for (int idx = tid; idx < 32 * 32; idx += 256) {
        int sl = idx >> 5, j = idx & 31;
        float a = b1[j];
        const float* hrow = hs0 + sl * 64;
#pragma unroll 8
        for (int k = 0; k < 64; ++k) a += hrow[k] * W1[k * 32 + j];
        t1[sl * 32 + j] = fmaxf(a, 0.f);
    }
    __syncthreads();
    for (int idx = tid; idx < 32 * 12; idx += 256) {
        int sl = idx / 12, p = idx - sl * 12;
        float a = b2[p];
        const float* trow = t1 + sl * 32;
#pragma unroll 8
        for (int k = 0; k < 32; ++k) a += trow[k] * W2[k * 12 + p];
        int sgl = s0 + sl;
        int bb = sgl >> 9, n = sgl & 511;
        out[(bb * 12 + p) * 512 + n] = a;
    }
}

extern "C" void kernel_launch(void* const* d_in, const int* in_sizes, int n_in,
                              void* d_out, int out_size)
{
    const float* X   = (const float*)d_in[0];
    const int*   Gs  = (const int*)d_in[1];
    const int*   Gn  = (const int*)d_in[2];
    const int*   Gd  = (const int*)d_in[3];
    const float* Wg  = (const float*)d_in[4];
    const float* a1g = (const float*)d_in[5];
    const float* a2g = (const float*)d_in[6];
    const float* Wn  = (const float*)d_in[7];
    const float* a1n = (const float*)d_in[8];
    const float* a2n = (const float*)d_in[9];
    const float* Wd  = (const float*)d_in[10];
    const float* a1d = (const float*)d_in[11];
    const float* a2d = (const float*)d_in[12];
    const float* Wf  = (const float*)d_in[13];
    const float* bf  = (const float*)d_in[14];
    const float* Wih = (const float*)d_in[15];
    const float* Whh = (const float*)d_in[16];
    const float* bih = (const float*)d_in[17];
    const float* bhh = (const float*)d_in[18];
    const float* W1  = (const float*)d_in[19];
    const float* b1  = (const float*)d_in[20];
    const float* W2  = (const float*)d_in[21];
    const float* b2  = (const float*)d_in[22];
    float* out = (float*)d_out;

    cudaFuncSetAttribute(gat_kernel,     cudaFuncAttributeMaxDynamicSharedMemorySize, SMEM_K1);
    cudaFuncSetAttribute(spatial_kernel, cudaFuncAttributeMaxDynamicSharedMemorySize, SMEM_B1);
    cudaFuncSetAttribute(gx_kernel,      cudaFuncAttributeMaxDynamicSharedMemorySize, SMEM_B2);
    cudaFuncSetAttribute(gru_kernel,     cudaFuncAttributeMaxDynamicSharedMemorySize, SMEM_C);

    prep_kernel<<<dim3(4, 64), 256>>>(Gs, Gn, Gd, Wf, Wih);
    gat_kernel<<<dim3(96, 8), 256, SMEM_K1>>>(X, Wg, a1g, a2g, Wn, a1n, a2n, Wd, a1d, a2d);
    spatial_kernel<<<dim3(96, 8), 256, SMEM_B1>>>(bf);
    gx_kernel<<<dim3(96, 16), 192, SMEM_B2>>>(X, bih);
    gru_kernel<<<128, 256, SMEM_C>>>(Whh, bhh, W1, b1, W2, b2, out);
}

// round 13
// speedup vs baseline: 1.2319x; 1.0032x over previous
#include <cuda_runtime.h>
#include <math.h>

// ---------------------------------------------------------------
// BSTGCNet R13 = R10 (best: 217.8us) with gx-only restructure:
// k4 outer loop + 32 row-accumulators in regs -> each weight LDG
// feeds 64 fma2 while weight reg pressure is ~4 regs (was 68).
// B=8, T=12, N=512, FIN=2, H=64, P=12
// ---------------------------------------------------------------

typedef unsigned long long ull;

__device__ __forceinline__ ull fma2(ull a, ull b, ull c) {
    ull d; asm("fma.rn.f32x2 %0, %1, %2, %3;" : "=l"(d) : "l"(a), "l"(b), "l"(c)); return d;
}
__device__ __forceinline__ float hsum2(ull v) {
    float a, b; asm("mov.b64 {%0, %1}, %2;" : "=f"(a), "=f"(b) : "l"(v)); return a + b;
}

__device__ unsigned g_mask[3 * 512 * 16];       // packed adjacency bits
__device__ float g_feat[96 * 512 * 128];        // [f_s | f_nd] concat
__device__ float g_spatial[96 * 512 * 64];      // relu(concat@Wf+bf)
__device__ float g_gx[4096 * 12 * 192];         // input transform for GRU
__device__ ulonglong2 g_WfT2[32 * 64];          // Wf  [k4][h]
__device__ ulonglong2 g_WihT2[17 * 192];        // Wih [k4][g], k>=66 -> 0

#define SMEM_K1 ((512*2 + 512*4*2 + 3*128*2) * 4)            // 25600
#define SMEM_B1 (64*32*16)                                   // 32768
#define SMEM_B2 (32*17*16)                                   // 8704
#define SMEM_C  (32*192*8 + 2*32*64*4 + 32*32*4)             // 69632

// ----------------- prep: bitmasks + weight transposes -----------------
__global__ void prep_kernel(const int* __restrict__ Gs, const int* __restrict__ Gn,
                            const int* __restrict__ Gd,
                            const float* __restrict__ Wf, const float* __restrict__ Wih)
{
    const int g = blockIdx.x;
    if (g < 3) {
        const int row = blockIdx.y * 8 + (threadIdx.x >> 5);
        const int lane = threadIdx.x & 31;
        const int* adj = (g == 0) ? Gs : (g == 1) ? Gn : Gd;
        const int* arow = adj + row * 512;
#pragma unroll
        for (int it = 0; it < 16; ++it) {
            unsigned m = __ballot_sync(0xffffffffu, arow[it * 32 + lane] > 0);
            if (lane == 0) g_mask[(g * 512 + row) * 16 + it] = m;
        }
    } else {
        const int tid = blockIdx.y * 256 + threadIdx.x;
        if (tid < 32 * 64) {
            int k4 = tid >> 6, h = tid & 63;
            float4 v = make_float4(Wf[(4 * k4 + 0) * 64 + h], Wf[(4 * k4 + 1) * 64 + h],
                                   Wf[(4 * k4 + 2) * 64 + h], Wf[(4 * k4 + 3) * 64 + h]);
            g_WfT2[tid] = *(ulonglong2*)&v;
        }
        int t2 = tid - 32 * 64;
        if (t2 >= 0 && t2 < 17 * 192) {
            int k4 = t2 / 192, gg = t2 - k4 * 192;
            float w[4];
#pragma unroll
            for (int j = 0; j < 4; ++j) {
                int k = 4 * k4 + j;
                w[j] = (k < 66) ? Wih[gg * 66 + k] : 0.f;
            }
            g_WihT2[t2] = *(ulonglong2*)w;
        }
    }
}

// ----------------- K1: 3x GAT (rank-2) + concat features -----------------
// grid (96, 4), block 256. Each block: one m, 128 rows, all 3 gats.
__global__ void gat_kernel(const float* __restrict__ X,
                           const float* __restrict__ Wg, const float* __restrict__ a1g, const float* __restrict__ a2g,
                           const float* __restrict__ Wn, const float* __restrict__ a1n, const float* __restrict__ a2n,
                           const float* __restrict__ Wd, const float* __restrict__ a1d, const float* __restrict__ a2d)
{
    extern __shared__ float sm[];
    float*  x0s = sm;                       // 512
    float*  x1s = sm + 512;                 // 512
    float4* P4  = (float4*)(sm + 1024);     // 512  {E1*x0, E1*x1, E1, s2}
    float4* Q4  = P4 + 512;                 // 512  {E2*x0, E2*x1, E2, 0}
    float2* yg  = (float2*)(Q4 + 512);      // [3][128]

    const int m = blockIdx.x;
    const int row0 = blockIdx.y * 128;
    const int tid = threadIdx.x;
    const int lane = tid & 31, wid = tid >> 5;

    const float* Ws[3]  = {Wg, Wn, Wd};
    const float* A1s[3] = {a1g, a1n, a1d};
    const float* A2s[3] = {a2g, a2n, a2d};

    for (int i = tid; i < 512; i += 256) {
        x0s[i] = X[(m * 512 + i) * 2];
        x1s[i] = X[(m * 512 + i) * 2 + 1];
    }

    for (int g = 0; g < 3; ++g) {
        const float* W  = Ws[g];
        const float* a1 = A1s[g];
        const float* a2 = A2s[g];
        float c1a = 0.f, c1b = 0.f, c2a = 0.f, c2b = 0.f;
#pragma unroll 8
        for (int k = 0; k < 64; ++k) {
            float A1 = __ldg(a1 + k), A2 = __ldg(a2 + k);
            float u = __ldg(W + k), v = __ldg(W + 64 + k);
            c1a += u * A1; c1b += v * A1; c2a += u * A2; c2b += v * A2;
        }
        __syncthreads();
        for (int j = tid; j < 512; j += 256) {
            float x0 = x0s[j], x1 = x1s[j];
            float s2 = x0 * c2a + x1 * c2b;
            float E1 = __expf(s2);
            float E2 = __expf(0.2f * s2);
            P4[j] = make_float4(E1 * x0, E1 * x1, E1, s2);
            Q4[j] = make_float4(E2 * x0, E2 * x1, E2, 0.f);
        }
        __syncthreads();

        // 16 rows per warp, 4 rows per sweep
        for (int g4 = 0; g4 < 4; ++g4) {
            int rlb = wid * 16 + g4 * 4;
            float thr[4], Ae[4], Be[4];
            const unsigned* mr[4];
#pragma unroll
            for (int r = 0; r < 4; ++r) {
                int i = row0 + rlb + r;
                float s1 = x0s[i] * c1a + x1s[i] * c1b;
                thr[r] = -s1;
                Ae[r] = __expf(s1);
                Be[r] = __expf(0.2f * s1);
                mr[r] = g_mask + (g * 512 + i) * 16;
            }
            float a0[4], a1v[4], a2v[4], b0[4], b1v[4], b2v[4];
#pragma unroll
            for (int r = 0; r < 4; ++r) {
                a0[r] = a1v[r] = a2v[r] = 0.f;
                b0[r] = b1v[r] = b2v[r] = 0.f;
            }
            for (int it = 0; it < 16; ++it) {
                int j = it * 32 + lane;
                float4 p = P4[j];
                float4 q = Q4[j];
#pragma unroll
                for (int r = 0; r < 4; ++r) {
                    unsigned mw = __ldg(mr[r] + it);
                    if ((mw >> lane) & 1u) {
                        if (p.w > thr[r]) { a0[r] += p.x; a1v[r] += p.y; a2v[r] += p.z; }
                        else              { b0[r] += q.x; b1v[r] += q.y; b2v[r] += q.z; }
                    }
                }
            }
#pragma unroll
            for (int r = 0; r < 4; ++r) {
                float y0 = Ae[r] * a0[r] + Be[r] * b0[r];
                float y1 = Ae[r] * a1v[r] + Be[r] * b1v[r];
                float Z  = Ae[r] * a2v[r] + Be[r] * b2v[r];
#pragma unroll
                for (int o = 16; o; o >>= 1) {
                    y0 += __shfl_xor_sync(0xffffffffu, y0, o);
                    y1 += __shfl_xor_sync(0xffffffffu, y1, o);
                    Z  += __shfl_xor_sync(0xffffffffu, Z, o);
                }
                if (lane == 0) {
                    float zi = __fdividef(1.f, Z);
                    yg[g * 128 + rlb + r] = make_float2(y0 * zi, y1 * zi);
                }
            }
        }
    }
    __syncthreads();

    const int h = tid & 63;
    const float wg0 = __ldg(Wg + h), wg1 = __ldg(Wg + 64 + h);
    const float wn0 = __ldg(Wn + h), wn1 = __ldg(Wn + 64 + h);
    const float wd0 = __ldg(Wd + h), wd1 = __ldg(Wd + 64 + h);
#pragma unroll 4
    for (int it = 0; it < 32; ++it) {
        int rl = (tid >> 6) + it * 4;
        float2 ys = yg[rl], yn = yg[128 + rl], yd = yg[256 + rl];
        float vs = ys.x * wg0 + ys.y * wg1;
        vs = (vs > 0.f) ? vs : (__expf(vs) - 1.f);
        float vn = yn.x * wn0 + yn.y * wn1;
        vn = (vn > 0.f) ? vn : (__expf(vn) - 1.f);
        float vd = yd.x * wd0 + yd.y * wd1;
        vd = (vd > 0.f) ? vd : (__expf(vd) - 1.f);
        int gi = (m * 512 + row0 + rl) * 128;
        g_feat[gi + h] = vs;
        g_feat[gi + 64 + h] = vn + vd;
    }
}

// ----------------- B1: spatial fuse -----------------
// grid (96, 8), block 256, 64 rows/block. Each thread: 2 h-cols x 8 rows.
__global__ void spatial_kernel(const float* __restrict__ bf)
{
    extern __shared__ ulonglong2 smu[];      // feat rows [64][32]
    const int m = blockIdx.x, row0 = blockIdx.y * 64;
    const int tid = threadIdx.x, lane = tid & 31, rg = tid >> 5;

    const float4* src = (const float4*)(g_feat + (m * 512 + row0) * 128);
    float4* dst = (float4*)smu;
    for (int idx = tid; idx < 64 * 32; idx += 256) dst[idx] = src[idx];
    __syncthreads();

    const float bha = __ldg(bf + lane), bhb = __ldg(bf + 32 + lane);
    ull acca[8], accb[8];
#pragma unroll
    for (int r = 0; r < 8; ++r) { acca[r] = 0ull; accb[r] = 0ull; }
#pragma unroll 4
    for (int k4 = 0; k4 < 32; ++k4) {
        ulonglong2 wa = __ldg(&g_WfT2[k4 * 64 + lane]);
        ulonglong2 wb = __ldg(&g_WfT2[k4 * 64 + 32 + lane]);
#pragma unroll
        for (int r = 0; r < 8; ++r) {
            ulonglong2 fv = smu[(rg * 8 + r) * 32 + k4];
            acca[r] = fma2(wa.x, fv.x, acca[r]);
            acca[r] = fma2(wa.y, fv.y, acca[r]);
            accb[r] = fma2(wb.x, fv.x, accb[r]);
            accb[r] = fma2(wb.y, fv.y, accb[r]);
        }
    }
#pragma unroll
    for (int r = 0; r < 8; ++r) {
        float* orow = g_spatial + (m * 512 + row0 + rg * 8 + r) * 64;
        orow[lane]      = fmaxf(hsum2(acca[r]) + bha, 0.f);
        orow[32 + lane] = fmaxf(hsum2(accb[r]) + bhb, 0.f);
    }
}

// ----------------- B2: gx = [spatial,x] @ W_ih^T + b_ih -----------------
// grid (96, 16), block 192, 32 rows/block. k4 OUTER loop, 32 row-accs
// in regs: each weight LDG.128 feeds 64 fma2; weight reg pressure ~4.
__global__ void gx_kernel(const float* __restrict__ X, const float* __restrict__ bih)
{
    extern __shared__ ulonglong2 smu[];      // gru_in rows [32][17]
    float* smf = (float*)smu;
    const int m = blockIdx.x;
    const int b = m / 12, t = m - b * 12;
    const int row0 = blockIdx.y * 32;
    const int tid = threadIdx.x;             // = gate dim g

    for (int idx = tid; idx < 32 * 68; idx += 192) {
        int r = idx / 68, k = idx - r * 68;
        float v;
        if (k < 64)      v = g_spatial[(m * 512 + row0 + r) * 64 + k];
        else if (k < 66) v = X[(m * 512 + row0 + r) * 2 + (k - 64)];
        else             v = 0.f;
        smf[idx] = v;
    }
    __syncthreads();

    const int g = tid;
    const float bg = __ldg(bih + g);

    ull acc2[32];
#pragma unroll
    for (int r = 0; r < 32; ++r) acc2[r] = 0ull;

#pragma unroll
    for (int k4 = 0; k4 < 17; ++k4) {
        ulonglong2 wv = __ldg(&g_WihT2[k4 * 192 + g]);
#pragma unroll
        for (int r = 0; r < 32; ++r) {
            ulonglong2 hv = smu[r * 17 + k4];
            acc2[r] = fma2(wv.x, hv.x, acc2[r]);
            acc2[r] = fma2(wv.y, hv.y, acc2[r]);
        }
    }

    float* gxout = g_gx + ((b * 512 + row0) * 12 + t) * 192 + g;
#pragma unroll
    for (int r = 0; r < 32; ++r)
        gxout[r * 12 * 192] = hsum2(acc2[r]) + bg;
}

// ----------------- K3: GRU recurrence + heads -----------------
// grid 128, block 256. 32 seqs/block, 8 seqs per thread group.
__global__ void gru_kernel(const float* __restrict__ Whh, const float* __restrict__ bhh,
                           const float* __restrict__ W1, const float* __restrict__ b1,
                           const float* __restrict__ W2, const float* __restrict__ b2,
                           float* __restrict__ out)
{
    extern __shared__ float sm[];
    float* wt  = sm;                    // [32][192][2]
    float* hs0 = sm + 12288;            // [32][64]
    float* hs1 = hs0 + 32 * 64;         // [32][64]
    float* t1  = hs1 + 32 * 64;         // [32][32]
    const int tid = threadIdx.x;
    const int h = tid & 63, sg = tid >> 6;

    for (int idx = tid; idx < 12288; idx += 256) {
        int e = idx & 1, rest = idx >> 1;
        int row = rest % 192, k2 = rest / 192;
        wt[idx] = Whh[row * 64 + k2 * 2 + e];
    }
    for (int idx = tid; idx < 32 * 64; idx += 256) hs0[idx] = 0.f;
    __syncthreads();

    const float bhr = bhh[h], bhz = bhh[64 + h], bhn = bhh[128 + h];
    const int s0 = blockIdx.x * 32;
    const ull* wp = (const ull*)wt;

    for (int t = 0; t < 12; ++t) {
        float* cur = (t & 1) ? hs1 : hs0;
        float* nxt = (t & 1) ? hs0 : hs1;

        float gxr[8], gxz[8], gxn[8];
#pragma unroll
        for (int si = 0; si < 8; ++si) {
            const float* gxp = g_gx + ((s0 + sg * 8 + si) * 12 + t) * 192;
            gxr[si] = gxp[h]; gxz[si] = gxp[64 + h]; gxn[si] = gxp[128 + h];
        }

        ull ar2[8], az2[8], an2[8];
#pragma unroll
        for (int si = 0; si < 8; ++si) { ar2[si] = 0ull; az2[si] = 0ull; an2[si] = 0ull; }
        const ull* hc = (const ull*)(cur + sg * 8 * 64);
#pragma unroll 4
        for (int k2 = 0; k2 < 32; ++k2) {
            ull wr = wp[k2 * 192 + h];
            ull wz = wp[k2 * 192 + 64 + h];
            ull wn = wp[k2 * 192 + 128 + h];
#pragma unroll
            for (int si = 0; si < 8; ++si) {
                ull hp = hc[si * 32 + k2];
                ar2[si] = fma2(wr, hp, ar2[si]);
                az2[si] = fma2(wz, hp, az2[si]);
                an2[si] = fma2(wn, hp, an2[si]);
            }
        }
#pragma unroll
        for (int si = 0; si < 8; ++si) {
            int sl = sg * 8 + si;
            float r = __fdividef(1.f, 1.f + __expf(-(gxr[si] + hsum2(ar2[si]) + bhr)));
            float z = __fdividef(1.f, 1.f + __expf(-(gxz[si] + hsum2(az2[si]) + bhz)));
            float narg = gxn[si] + r * (hsum2(an2[si]) + bhn);
            float ex = __expf(-2.f * narg);
            float n = 1.f - __fdividef(2.f * ex, 1.f + ex);
            float hp = cur[sl * 64 + h];
            nxt[sl * 64 + h] = (1.f - z) * n + z * hp;
        }
        __syncthreads();
    }

    // heads: relu(h@W1+b1)@W2+b2 ; final h in hs0 (T=12 even)
    for (int idx = tid; idx < 32 * 32; idx += 256) {
        int sl = idx >> 5, j = idx & 31;
        float a = b1[j];
        const float* hrow = hs0 + sl * 64;
#pragma unroll 8
        for (int k = 0; k < 64; ++k) a += hrow[k] * W1[k * 32 + j];
        t1[sl * 32 + j] = fmaxf(a, 0.f);
    }
    __syncthreads();
    for (int idx = tid; idx < 32 * 12; idx += 256) {
        int sl = idx / 12, p = idx - sl * 12;
        float a = b2[p];
        const float* trow = t1 + sl * 32;
#pragma unroll 8
        for (int k = 0; k < 32; ++k) a += trow[k] * W2[k * 12 + p];
        int sgl = s0 + sl;
        int bb = sgl >> 9, n = sgl & 511;
        out[(bb * 12 + p) * 512 + n] = a;
    }
}

extern "C" void kernel_launch(void* const* d_in, const int* in_sizes, int n_in,
                              void* d_out, int out_size)
{
    const float* X   = (const float*)d_in[0];
    const int*   Gs  = (const int*)d_in[1];
    const int*   Gn  = (const int*)d_in[2];
    const int*   Gd  = (const int*)d_in[3];
    const float* Wg  = (const float*)d_in[4];
    const float* a1g = (const float*)d_in[5];
    const float* a2g = (const float*)d_in[6];
    const float* Wn  = (const float*)d_in[7];
    const float* a1n = (const float*)d_in[8];
    const float* a2n = (const float*)d_in[9];
    const float* Wd  = (const float*)d_in[10];
    const float* a1d = (const float*)d_in[11];
    const float* a2d = (const float*)d_in[12];
    const float* Wf  = (const float*)d_in[13];
    const float* bf  = (const float*)d_in[14];
    const float* Wih = (const float*)d_in[15];
    const float* Whh = (const float*)d_in[16];
    const float* bih = (const float*)d_in[17];
    const float* bhh = (const float*)d_in[18];
    const float* W1  = (const float*)d_in[19];
    const float* b1  = (const float*)d_in[20];
    const float* W2  = (const float*)d_in[21];
    const float* b2  = (const float*)d_in[22];
    float* out = (float*)d_out;

    cudaFuncSetAttribute(gat_kernel,     cudaFuncAttributeMaxDynamicSharedMemorySize, SMEM_K1);
    cudaFuncSetAttribute(spatial_kernel, cudaFuncAttributeMaxDynamicSharedMemorySize, SMEM_B1);
    cudaFuncSetAttribute(gx_kernel,      cudaFuncAttributeMaxDynamicSharedMemorySize, SMEM_B2);
    cudaFuncSetAttribute(gru_kernel,     cudaFuncAttributeMaxDynamicSharedMemorySize, SMEM_C);

    prep_kernel<<<dim3(4, 64), 256>>>(Gs, Gn, Gd, Wf, Wih);
    gat_kernel<<<dim3(96, 4), 256, SMEM_K1>>>(X, Wg, a1g, a2g, Wn, a1n, a2n, Wd, a1d, a2d);
    spatial_kernel<<<dim3(96, 8), 256, SMEM_B1>>>(bf);
    gx_kernel<<<dim3(96, 16), 192, SMEM_B2>>>(X, bih);
    gru_kernel<<<128, 256, SMEM_C>>>(Whh, bhh, W1, b1, W2, b2, out);
}

// round 14
// speedup vs baseline: 1.3098x; 1.0632x over previous
#include <cuda_runtime.h>
#include <math.h>

// ---------------------------------------------------------------
// BSTGCNet R14 = R10 (best: 217.8us) with gx-only change:
// 16 rows/block (grid (96,32)), k4-outer, acc2[16] -> ~70 regs
// -> 4 CTAs/SM (37.5% occ) while keeping 32 fma2 per weight LDG.
// B=8, T=12, N=512, FIN=2, H=64, P=12
// ---------------------------------------------------------------

typedef unsigned long long ull;

__device__ __forceinline__ ull fma2(ull a, ull b, ull c) {
    ull d; asm("fma.rn.f32x2 %0, %1, %2, %3;" : "=l"(d) : "l"(a), "l"(b), "l"(c)); return d;
}
__device__ __forceinline__ float hsum2(ull v) {
    float a, b; asm("mov.b64 {%0, %1}, %2;" : "=f"(a), "=f"(b) : "l"(v)); return a + b;
}

__device__ unsigned g_mask[3 * 512 * 16];       // packed adjacency bits
__device__ float g_feat[96 * 512 * 128];        // [f_s | f_nd] concat
__device__ float g_spatial[96 * 512 * 64];      // relu(concat@Wf+bf)
__device__ float g_gx[4096 * 12 * 192];         // input transform for GRU
__device__ ulonglong2 g_WfT2[32 * 64];          // Wf  [k4][h]
__device__ ulonglong2 g_WihT2[17 * 192];        // Wih [k4][g], k>=66 -> 0

#define SMEM_K1 ((512*2 + 512*4*2 + 3*128*2) * 4)            // 25600
#define SMEM_B1 (64*32*16)                                   // 32768
#define SMEM_B2 (16*17*16)                                   // 4352
#define SMEM_C  (32*192*8 + 2*32*64*4 + 32*32*4)             // 69632

// ----------------- prep: bitmasks + weight transposes -----------------
__global__ void prep_kernel(const int* __restrict__ Gs, const int* __restrict__ Gn,
                            const int* __restrict__ Gd,
                            const float* __restrict__ Wf, const float* __restrict__ Wih)
{
    const int g = blockIdx.x;
    if (g < 3) {
        const int row = blockIdx.y * 8 + (threadIdx.x >> 5);
        const int lane = threadIdx.x & 31;
        const int* adj = (g == 0) ? Gs : (g == 1) ? Gn : Gd;
        const int* arow = adj + row * 512;
#pragma unroll
        for (int it = 0; it < 16; ++it) {
            unsigned m = __ballot_sync(0xffffffffu, arow[it * 32 + lane] > 0);
            if (lane == 0) g_mask[(g * 512 + row) * 16 + it] = m;
        }
    } else {
        const int tid = blockIdx.y * 256 + threadIdx.x;
        if (tid < 32 * 64) {
            int k4 = tid >> 6, h = tid & 63;
            float4 v = make_float4(Wf[(4 * k4 + 0) * 64 + h], Wf[(4 * k4 + 1) * 64 + h],
                                   Wf[(4 * k4 + 2) * 64 + h], Wf[(4 * k4 + 3) * 64 + h]);
            g_WfT2[tid] = *(ulonglong2*)&v;
        }
        int t2 = tid - 32 * 64;
        if (t2 >= 0 && t2 < 17 * 192) {
            int k4 = t2 / 192, gg = t2 - k4 * 192;
            float w[4];
#pragma unroll
            for (int j = 0; j < 4; ++j) {
                int k = 4 * k4 + j;
                w[j] = (k < 66) ? Wih[gg * 66 + k] : 0.f;
            }
            g_WihT2[t2] = *(ulonglong2*)w;
        }
    }
}

// ----------------- K1: 3x GAT (rank-2) + concat features -----------------
// grid (96, 4), block 256. Each block: one m, 128 rows, all 3 gats.
__global__ void gat_kernel(const float* __restrict__ X,
                           const float* __restrict__ Wg, const float* __restrict__ a1g, const float* __restrict__ a2g,
                           const float* __restrict__ Wn, const float* __restrict__ a1n, const float* __restrict__ a2n,
                           const float* __restrict__ Wd, const float* __restrict__ a1d, const float* __restrict__ a2d)
{
    extern __shared__ float sm[];
    float*  x0s = sm;                       // 512
    float*  x1s = sm + 512;                 // 512
    float4* P4  = (float4*)(sm + 1024);     // 512  {E1*x0, E1*x1, E1, s2}
    float4* Q4  = P4 + 512;                 // 512  {E2*x0, E2*x1, E2, 0}
    float2* yg  = (float2*)(Q4 + 512);      // [3][128]

    const int m = blockIdx.x;
    const int row0 = blockIdx.y * 128;
    const int tid = threadIdx.x;
    const int lane = tid & 31, wid = tid >> 5;

    const float* Ws[3]  = {Wg, Wn, Wd};
    const float* A1s[3] = {a1g, a1n, a1d};
    const float* A2s[3] = {a2g, a2n, a2d};

    for (int i = tid; i < 512; i += 256) {
        x0s[i] = X[(m * 512 + i) * 2];
        x1s[i] = X[(m * 512 + i) * 2 + 1];
    }

    for (int g = 0; g < 3; ++g) {
        const float* W  = Ws[g];
        const float* a1 = A1s[g];
        const float* a2 = A2s[g];
        float c1a = 0.f, c1b = 0.f, c2a = 0.f, c2b = 0.f;
#pragma unroll 8
        for (int k = 0; k < 64; ++k) {
            float A1 = __ldg(a1 + k), A2 = __ldg(a2 + k);
            float u = __ldg(W + k), v = __ldg(W + 64 + k);
            c1a += u * A1; c1b += v * A1; c2a += u * A2; c2b += v * A2;
        }
        __syncthreads();
        for (int j = tid; j < 512; j += 256) {
            float x0 = x0s[j], x1 = x1s[j];
            float s2 = x0 * c2a + x1 * c2b;
            float E1 = __expf(s2);
            float E2 = __expf(0.2f * s2);
            P4[j] = make_float4(E1 * x0, E1 * x1, E1, s2);
            Q4[j] = make_float4(E2 * x0, E2 * x1, E2, 0.f);
        }
        __syncthreads();

        // 16 rows per warp, 4 rows per sweep
        for (int g4 = 0; g4 < 4; ++g4) {
            int rlb = wid * 16 + g4 * 4;
            float thr[4], Ae[4], Be[4];
            const unsigned* mr[4];
#pragma unroll
            for (int r = 0; r < 4; ++r) {
                int i = row0 + rlb + r;
                float s1 = x0s[i] * c1a + x1s[i] * c1b;
                thr[r] = -s1;
                Ae[r] = __expf(s1);
                Be[r] = __expf(0.2f * s1);
                mr[r] = g_mask + (g * 512 + i) * 16;
            }
            float a0[4], a1v[4], a2v[4], b0[4], b1v[4], b2v[4];
#pragma unroll
            for (int r = 0; r < 4; ++r) {
                a0[r] = a1v[r] = a2v[r] = 0.f;
                b0[r] = b1v[r] = b2v[r] = 0.f;
            }
            for (int it = 0; it < 16; ++it) {
                int j = it * 32 + lane;
                float4 p = P4[j];
                float4 q = Q4[j];
#pragma unroll
                for (int r = 0; r < 4; ++r) {
                    unsigned mw = __ldg(mr[r] + it);
                    if ((mw >> lane) & 1u) {
                        if (p.w > thr[r]) { a0[r] += p.x; a1v[r] += p.y; a2v[r] += p.z; }
                        else              { b0[r] += q.x; b1v[r] += q.y; b2v[r] += q.z; }
                    }
                }
            }
#pragma unroll
            for (int r = 0; r < 4; ++r) {
                float y0 = Ae[r] * a0[r] + Be[r] * b0[r];
                float y1 = Ae[r] * a1v[r] + Be[r] * b1v[r];
                float Z  = Ae[r] * a2v[r] + Be[r] * b2v[r];
#pragma unroll
                for (int o = 16; o; o >>= 1) {
                    y0 += __shfl_xor_sync(0xffffffffu, y0, o);
                    y1 += __shfl_xor_sync(0xffffffffu, y1, o);
                    Z  += __shfl_xor_sync(0xffffffffu, Z, o);
                }
                if (lane == 0) {
                    float zi = __fdividef(1.f, Z);
                    yg[g * 128 + rlb + r] = make_float2(y0 * zi, y1 * zi);
                }
            }
        }
    }
    __syncthreads();

    const int h = tid & 63;
    const float wg0 = __ldg(Wg + h), wg1 = __ldg(Wg + 64 + h);
    const float wn0 = __ldg(Wn + h), wn1 = __ldg(Wn + 64 + h);
    const float wd0 = __ldg(Wd + h), wd1 = __ldg(Wd + 64 + h);
#pragma unroll 4
    for (int it = 0; it < 32; ++it) {
        int rl = (tid >> 6) + it * 4;
        float2 ys = yg[rl], yn = yg[128 + rl], yd = yg[256 + rl];
        float vs = ys.x * wg0 + ys.y * wg1;
        vs = (vs > 0.f) ? vs : (__expf(vs) - 1.f);
        float vn = yn.x * wn0 + yn.y * wn1;
        vn = (vn > 0.f) ? vn : (__expf(vn) - 1.f);
        float vd = yd.x * wd0 + yd.y * wd1;
        vd = (vd > 0.f) ? vd : (__expf(vd) - 1.f);
        int gi = (m * 512 + row0 + rl) * 128;
        g_feat[gi + h] = vs;
        g_feat[gi + 64 + h] = vn + vd;
    }
}

// ----------------- B1: spatial fuse -----------------
// grid (96, 8), block 256, 64 rows/block. Each thread: 2 h-cols x 8 rows.
__global__ void spatial_kernel(const float* __restrict__ bf)
{
    extern __shared__ ulonglong2 smu[];      // feat rows [64][32]
    const int m = blockIdx.x, row0 = blockIdx.y * 64;
    const int tid = threadIdx.x, lane = tid & 31, rg = tid >> 5;

    const float4* src = (const float4*)(g_feat + (m * 512 + row0) * 128);
    float4* dst = (float4*)smu;
    for (int idx = tid; idx < 64 * 32; idx += 256) dst[idx] = src[idx];
    __syncthreads();

    const float bha = __ldg(bf + lane), bhb = __ldg(bf + 32 + lane);
    ull acca[8], accb[8];
#pragma unroll
    for (int r = 0; r < 8; ++r) { acca[r] = 0ull; accb[r] = 0ull; }
#pragma unroll 4
    for (int k4 = 0; k4 < 32; ++k4) {
        ulonglong2 wa = __ldg(&g_WfT2[k4 * 64 + lane]);
        ulonglong2 wb = __ldg(&g_WfT2[k4 * 64 + 32 + lane]);
#pragma unroll
        for (int r = 0; r < 8; ++r) {
            ulonglong2 fv = smu[(rg * 8 + r) * 32 + k4];
            acca[r] = fma2(wa.x, fv.x, acca[r]);
            acca[r] = fma2(wa.y, fv.y, acca[r]);
            accb[r] = fma2(wb.x, fv.x, accb[r]);
            accb[r] = fma2(wb.y, fv.y, accb[r]);
        }
    }
#pragma unroll
    for (int r = 0; r < 8; ++r) {
        float* orow = g_spatial + (m * 512 + row0 + rg * 8 + r) * 64;
        orow[lane]      = fmaxf(hsum2(acca[r]) + bha, 0.f);
        orow[32 + lane] = fmaxf(hsum2(accb[r]) + bhb, 0.f);
    }
}

// ----------------- B2: gx = [spatial,x] @ W_ih^T + b_ih -----------------
// grid (96, 32), block 192, 16 rows/block. k4-outer, acc2[16] in regs:
// 32 fma2 per weight LDG at HALF the register pressure of R13.
__global__ void gx_kernel(const float* __restrict__ X, const float* __restrict__ bih)
{
    extern __shared__ ulonglong2 smu[];      // gru_in rows [16][17]
    float* smf = (float*)smu;
    const int m = blockIdx.x;
    const int b = m / 12, t = m - b * 12;
    const int row0 = blockIdx.y * 16;
    const int tid = threadIdx.x;             // = gate dim g

    for (int idx = tid; idx < 16 * 68; idx += 192) {
        int r = idx / 68, k = idx - r * 68;
        float v;
        if (k < 64)      v = g_spatial[(m * 512 + row0 + r) * 64 + k];
        else if (k < 66) v = X[(m * 512 + row0 + r) * 2 + (k - 64)];
        else             v = 0.f;
        smf[idx] = v;
    }
    __syncthreads();

    const int g = tid;
    const float bg = __ldg(bih + g);

    ull acc2[16];
#pragma unroll
    for (int r = 0; r < 16; ++r) acc2[r] = 0ull;

#pragma unroll
    for (int k4 = 0; k4 < 17; ++k4) {
        ulonglong2 wv = __ldg(&g_WihT2[k4 * 192 + g]);
#pragma unroll
        for (int r = 0; r < 16; ++r) {
            ulonglong2 hv = smu[r * 17 + k4];
            acc2[r] = fma2(wv.x, hv.x, acc2[r]);
            acc2[r] = fma2(wv.y, hv.y, acc2[r]);
        }
    }

    float* gxout = g_gx + ((b * 512 + row0) * 12 + t) * 192 + g;
#pragma unroll
    for (int r = 0; r < 16; ++r)
        gxout[r * 12 * 192] = hsum2(acc2[r]) + bg;
}

// ----------------- K3: GRU recurrence + heads -----------------
// grid 128, block 256. 32 seqs/block, 8 seqs per thread group.
__global__ void gru_kernel(const float* __restrict__ Whh, const float* __restrict__ bhh,
                           const float* __restrict__ W1, const float* __restrict__ b1,
                           const float* __restrict__ W2, const float* __restrict__ b2,
                           float* __restrict__ out)
{
    extern __shared__ float sm[];
    float* wt  = sm;                    // [32][192][2]
    float* hs0 = sm + 12288;            // [32][64]
    float* hs1 = hs0 + 32 * 64;         // [32][64]
    float* t1  = hs1 + 32 * 64;         // [32][32]
    const int tid = threadIdx.x;
    const int h = tid & 63, sg = tid >> 6;

    for (int idx = tid; idx < 12288; idx += 256) {
        int e = idx & 1, rest = idx >> 1;
        int row = rest % 192, k2 = rest / 192;
        wt[idx] = Whh[row * 64 + k2 * 2 + e];
    }
    for (int idx = tid; idx < 32 * 64; idx += 256) hs0[idx] = 0.f;
    __syncthreads();

    const float bhr = bhh[h], bhz = bhh[64 + h], bhn = bhh[128 + h];
    const int s0 = blockIdx.x * 32;
    const ull* wp = (const ull*)wt;

    for (int t = 0; t < 12; ++t) {
        float* cur = (t & 1) ? hs1 : hs0;
        float* nxt = (t & 1) ? hs0 : hs1;

        float gxr[8], gxz[8], gxn[8];
#pragma unroll
        for (int si = 0; si < 8; ++si) {
            const float* gxp = g_gx + ((s0 + sg * 8 + si) * 12 + t) * 192;
            gxr[si] = gxp[h]; gxz[si] = gxp[64 + h]; gxn[si] = gxp[128 + h];
        }

        ull ar2[8], az2[8], an2[8];
#pragma unroll
        for (int si = 0; si < 8; ++si) { ar2[si] = 0ull; az2[si] = 0ull; an2[si] = 0ull; }
        const ull* hc = (const ull*)(cur + sg * 8 * 64);
#pragma unroll 4
        for (int k2 = 0; k2 < 32; ++k2) {
            ull wr = wp[k2 * 192 + h];
            ull wz = wp[k2 * 192 + 64 + h];
            ull wn = wp[k2 * 192 + 128 + h];
#pragma unroll
            for (int si = 0; si < 8; ++si) {
                ull hp = hc[si * 32 + k2];
                ar2[si] = fma2(wr, hp, ar2[si]);
                az2[si] = fma2(wz, hp, az2[si]);
                an2[si] = fma2(wn, hp, an2[si]);
            }
        }
#pragma unroll
        for (int si = 0; si < 8; ++si) {
            int sl = sg * 8 + si;
            float r = __fdividef(1.f, 1.f + __expf(-(gxr[si] + hsum2(ar2[si]) + bhr)));
            float z = __fdividef(1.f, 1.f + __expf(-(gxz[si] + hsum2(az2[si]) + bhz)));
            float narg = gxn[si] + r * (hsum2(an2[si]) + bhn);
            float ex = __expf(-2.f * narg);
            float n = 1.f - __fdividef(2.f * ex, 1.f + ex);
            float hp = cur[sl * 64 + h];
            nxt[sl * 64 + h] = (1.f - z) * n + z * hp;
        }
        __syncthreads();
    }

    // heads: relu(h@W1+b1)@W2+b2 ; final h in hs0 (T=12 even)
    for (int idx = tid; idx < 32 * 32; idx += 256) {
        int sl = idx >> 5, j = idx & 31;
        float a = b1[j];
        const float* hrow = hs0 + sl * 64;
#pragma unroll 8
        for (int k = 0; k < 64; ++k) a += hrow[k] * W1[k * 32 + j];
        t1[sl * 32 + j] = fmaxf(a, 0.f);
    }
    __syncthreads();
    for (int idx = tid; idx < 32 * 12; idx += 256) {
        int sl = idx / 12, p = idx - sl * 12;
        float a = b2[p];
        const float* trow = t1 + sl * 32;
#pragma unroll 8
        for (int k = 0; k < 32; ++k) a += trow[k] * W2[k * 12 + p];
        int sgl = s0 + sl;
        int bb = sgl >> 9, n = sgl & 511;
        out[(bb * 12 + p) * 512 + n] = a;
    }
}

extern "C" void kernel_launch(void* const* d_in, const int* in_sizes, int n_in,
                              void* d_out, int out_size)
{
    const float* X   = (const float*)d_in[0];
    const int*   Gs  = (const int*)d_in[1];
    const int*   Gn  = (const int*)d_in[2];
    const int*   Gd  = (const int*)d_in[3];
    const float* Wg  = (const float*)d_in[4];
    const float* a1g = (const float*)d_in[5];
    const float* a2g = (const float*)d_in[6];
    const float* Wn  = (const float*)d_in[7];
    const float* a1n = (const float*)d_in[8];
    const float* a2n = (const float*)d_in[9];
    const float* Wd  = (const float*)d_in[10];
    const float* a1d = (const float*)d_in[11];
    const float* a2d = (const float*)d_in[12];
    const float* Wf  = (const float*)d_in[13];
    const float* bf  = (const float*)d_in[14];
    const float* Wih = (const float*)d_in[15];
    const float* Whh = (const float*)d_in[16];
    const float* bih = (const float*)d_in[17];
    const float* bhh = (const float*)d_in[18];
    const float* W1  = (const float*)d_in[19];
    const float* b1  = (const float*)d_in[20];
    const float* W2  = (const float*)d_in[21];
    const float* b2  = (const float*)d_in[22];
    float* out = (float*)d_out;

    cudaFuncSetAttribute(gat_kernel,     cudaFuncAttributeMaxDynamicSharedMemorySize, SMEM_K1);
    cudaFuncSetAttribute(spatial_kernel, cudaFuncAttributeMaxDynamicSharedMemorySize, SMEM_B1);
    cudaFuncSetAttribute(gx_kernel,      cudaFuncAttributeMaxDynamicSharedMemorySize, SMEM_B2);
    cudaFuncSetAttribute(gru_kernel,     cudaFuncAttributeMaxDynamicSharedMemorySize, SMEM_C);

    prep_kernel<<<dim3(4, 64), 256>>>(Gs, Gn, Gd, Wf, Wih);
    gat_kernel<<<dim3(96, 4), 256, SMEM_K1>>>(X, Wg, a1g, a2g, Wn, a1n, a2n, Wd, a1d, a2d);
    spatial_kernel<<<dim3(96, 8), 256, SMEM_B1>>>(bf);
    gx_kernel<<<dim3(96, 32), 192, SMEM_B2>>>(X, bih);
    gru_kernel<<<128, 256, SMEM_C>>>(Whh, bhh, W1, b1, W2, b2, out);
}